// round 16
// baseline (speedup 1.0000x reference)
#include <cuda_runtime.h>
#include <cuda_fp16.h>
#include <cstdint>
#include <math.h>

#define BSZ 1024
#define DIM 128
#define NB  32      // 32 row-blocks of 32 -> 528 upper-tri tiles

// ---------------- helpers --------------------------------------------------
__device__ __forceinline__ uint32_t smem_u32(const void* p) {
    uint32_t a;
    asm("{ .reg .u64 t; cvta.to.shared.u64 t, %1; cvt.u32.u64 %0, t; }"
        : "=r"(a) : "l"(p));
    return a;
}
#define LDSM4(r0, r1, r2, r3, addr) \
    asm volatile("ldmatrix.sync.aligned.m8n8.x4.shared.b16 {%0,%1,%2,%3}, [%4];" \
                 : "=r"(r0), "=r"(r1), "=r"(r2), "=r"(r3) : "r"(addr))
#define LDSM2(r0, r1, addr) \
    asm volatile("ldmatrix.sync.aligned.m8n8.x2.shared.b16 {%0,%1}, [%2];" \
                 : "=r"(r0), "=r"(r1) : "r"(addr))
#define MBARRIER_INIT(addr, cnt) \
    asm volatile("mbarrier.init.shared.b64 [%0], %1;" :: "r"(addr), "r"(cnt) : "memory")
#define MBARRIER_EXPECT_TX(addr, bytes) \
    asm volatile("mbarrier.arrive.expect_tx.shared.b64 _, [%0], %1;" \
                 :: "r"(addr), "r"((uint32_t)(bytes)) : "memory")
#define BULK_G2S(dst, src, bytes, mbar) \
    asm volatile("cp.async.bulk.shared::cta.global.mbarrier::complete_tx::bytes " \
                 "[%0], [%1], %2, [%3];" \
                 :: "r"(dst), "l"(src), "r"((uint32_t)(bytes)), "r"(mbar) : "memory")
#define MBARRIER_WAIT_PARITY(addr, par) do {                                      \
    uint32_t _m = (addr), _p = (par), _d;                                         \
    asm volatile("{\n\t.reg .pred p;\n\t"                                         \
        "mbarrier.try_wait.parity.acquire.cta.shared::cta.b64 p, [%1], %2;\n\t"   \
        "selp.b32 %0, 1, 0, p;\n\t}" : "=r"(_d) : "r"(_m), "r"(_p) : "memory");   \
    if (!_d) {                                                                    \
        asm volatile("{\n\t.reg .pred P1;\n\t"                                    \
            "WL_%=:\n\t"                                                          \
            "mbarrier.try_wait.parity.acquire.cta.shared::cta.b64 P1, [%0], %1, 0x989680;\n\t" \
            "@P1 bra.uni WD_%=;\n\tbra.uni WL_%=;\n\tWD_%=:\n\t}"                 \
            :: "r"(_m), "r"(_p) : "memory");                                      \
    }                                                                             \
} while (0)

__device__ __forceinline__ void mma_f16(float c[4],
                                        uint32_t a0, uint32_t a1, uint32_t a2, uint32_t a3,
                                        uint32_t b0, uint32_t b1) {
    asm volatile(
        "mma.sync.aligned.m16n8k16.row.col.f32.f16.f16.f32 "
        "{%0,%1,%2,%3}, {%4,%5,%6,%7}, {%8,%9}, {%0,%1,%2,%3};"
        : "+f"(c[0]), "+f"(c[1]), "+f"(c[2]), "+f"(c[3])
        : "r"(a0), "r"(a1), "r"(a2), "r"(a3), "r"(b0), "r"(b1));
}

// ---------------------------------------------------------------------------
// Fused kernel, 32x32 tiles: 528 upper-triangular CTAs, 256 threads (8 warps,
// warp grid 2m x 4n, warp tile 16x8), 2 CTAs/SM co-resident for latency
// overlap.  Uniform code path (diag CTAs stage/convert their own B copy).
// Phases: DMA x (mbar0) & dc (mbar1) -> convert x-part (A negated, +norms) ->
// MMA k0..7 -> convert dc-part -> MMA k8..15 -> epilogue (+ transpose via T).
//   smem: A @0 (32x528=16896) | B @16896 | S @33792 (4 x 16384)
//         T aliases A ; 99328 B dynamic.
// ---------------------------------------------------------------------------
#define ROWB   528
#define OFF_B  16896
#define OFF_S  33792
#define SMEM_BYTES 99328
#define TP 33   // transpose bounce pitch (floats)

__global__ void __launch_bounds__(256, 2)
fused_kernel(const float* __restrict__ x, const float* __restrict__ dc,
             const float* __restrict__ ap, float* __restrict__ out) {
    extern __shared__ __align__(16) char smem[];
    __shared__ __align__(8) uint64_t s_mbar[2];
    __shared__ float s_c[64];

    const int tid = threadIdx.x;
    const int wid = tid >> 5;
    const int lid = tid & 31;
    const int wm  = wid >> 2;          // 0..1 -> m offset wm*16
    const int wn  = wid & 3;           // 0..3 -> n offset wn*8

    // ---- decode upper-triangular tile (bi <= bj) ----
    int bi = 0, rem = blockIdx.x;
    while (rem >= NB - bi) { rem -= NB - bi; bi++; }
    const int bj = bi + rem;
    const int i0 = bi * 32;
    const int j0 = bj * 32;
    const bool diag = (bi == bj);

    const uint32_t sb = smem_u32(smem);
    const uint32_t mb = smem_u32(s_mbar);

    // ---- phase 0: issue DMAs (x under mbar0, dc under mbar1) ----
    if (tid == 0) {
        MBARRIER_INIT(mb, 1);
        MBARRIER_INIT(mb + 8, 1);
    }
    __syncthreads();
    if (tid == 0) {
        MBARRIER_EXPECT_TX(mb, 32768);
        BULK_G2S(sb + OFF_S,         x  + (size_t)i0 * DIM, 16384, mb);
        BULK_G2S(sb + OFF_S + 16384, x  + (size_t)j0 * DIM, 16384, mb);
        MBARRIER_EXPECT_TX(mb + 8, 32768);
        BULK_G2S(sb + OFF_S + 32768, dc + (size_t)i0 * DIM, 16384, mb + 8);
        BULK_G2S(sb + OFF_S + 49152, dc + (size_t)j0 * DIM, 16384, mb + 8);
    }

    const float a  = ap[0];
    const float s1 = sqrtf(2.0f * (1.0f - a));
    const float s2 = sqrtf(a);
    const int side = wid >> 2;              // 0: A rows (i), 1: B rows (j)
    const int wr   = (wid & 3) * 8;         // base row within side
    char* Dst = smem + side * OFF_B;
    const uint32_t sgn = side ? 0u : 0x80008000u;   // negate A's x-part

    // ---- phase 1: convert x-part (+ row norms) ----
    MBARRIER_WAIT_PARITY(mb, 0);
    {
        const char* S = smem + OFF_S + side * 16384;
#pragma unroll
        for (int r = 0; r < 8; r++) {
            const int lr = wr + r;
            const float4 xv = *(const float4*)(S + lr * 512 + lid * 16);
            __half zb[4] = { __float2half_rn(s1 * xv.x), __float2half_rn(s1 * xv.y),
                             __float2half_rn(s1 * xv.z), __float2half_rn(s1 * xv.w) };
            uint2 z2 = *(uint2*)zb;
            z2.x ^= sgn; z2.y ^= sgn;
            *(uint2*)(Dst + lr * ROWB + lid * 8) = z2;

            float s = xv.x * xv.x + xv.y * xv.y + xv.z * xv.z + xv.w * xv.w;
#pragma unroll
            for (int o = 16; o; o >>= 1) s += __shfl_down_sync(0xffffffffu, s, o);
            if (lid == 0) s_c[side * 32 + lr] = (1.0f - a) * s;
        }
    }
    __syncthreads();

    // ---- mainloop setup (warp tile 16x8: LDSM.x4 A + LDSM.x2 B + 1 MMA) ----
    const uint32_t aAd = sb + (wm * 16 + (lid & 15)) * ROWB + (lid >> 4) * 16;
    const uint32_t bAd = sb + OFF_B + (wn * 8 + (lid & 7)) * ROWB + ((lid >> 3) & 1) * 16;

    float acc[4] = {};
    uint32_t F[2][6];   // [set][ a0..3 | b0..1 ]

    auto ldf = [&](uint32_t* f, int ks) {
        const uint32_t ko = (uint32_t)ks * 32;
        LDSM4(f[0], f[1], f[2], f[3], aAd + ko);
        LDSM2(f[4], f[5], bAd + ko);
    };
    auto domma = [&](uint32_t* f) {
        mma_f16(acc, f[0], f[1], f[2], f[3], f[4], f[5]);
    };

    // ---- phase 2: k-steps 0..7 (x-part only) ----
    ldf(F[0], 0);
#pragma unroll
    for (int ks = 0; ks < 7; ks++) {
        ldf(F[(ks + 1) & 1], ks + 1);
        domma(F[ks & 1]);
    }
    domma(F[1]);

    // ---- phase 3: convert dc-part (own rows; x-cols untouched) ----
    MBARRIER_WAIT_PARITY(mb + 8, 0);
    {
        const char* Sd = smem + OFF_S + 32768 + side * 16384;
#pragma unroll
        for (int r = 0; r < 8; r++) {
            const int lr = wr + r;
            const float4 dv = *(const float4*)(Sd + lr * 512 + lid * 16);
            __half hb[4] = { __float2half_rn(s2 * __expf(1.0f - dv.x)),
                             __float2half_rn(s2 * __expf(1.0f - dv.y)),
                             __float2half_rn(s2 * __expf(1.0f - dv.z)),
                             __float2half_rn(s2 * __expf(1.0f - dv.w)) };
            *(uint2*)(Dst + lr * ROWB + 256 + lid * 8) = *(uint2*)hb;
        }
    }
    __syncthreads();

    // ---- phase 4: k-steps 8..15 (dc-part) ----
    ldf(F[0], 8);
#pragma unroll
    for (int ks = 8; ks < 15; ks++) {
        ldf(F[(ks + 1) & 1], ks + 1);
        domma(F[ks & 1]);
    }
    domma(F[1]);

    // ---- phase 5: epilogue ----
    const int g = lid >> 2;
    const int t = lid & 3;
    const int lia = wm * 16 + g;        // local A row
    const int lib = lia + 8;
    const int ia = i0 + lia;
    const int ib = i0 + lib;
    const int lj = wn * 8 + t * 2;
    const int j  = j0 + lj;
    const float cia = s_c[lia];
    const float cib = s_c[lib];
    const float cj0 = s_c[32 + lj];
    const float cj1 = s_c[32 + lj + 1];

    const float v00 = (ia == j)     ? 1.0f : __fdividef((float)DIM, cia + cj0 + acc[0]);
    const float v01 = (ia == j + 1) ? 1.0f : __fdividef((float)DIM, cia + cj1 + acc[1]);
    const float v10 = (ib == j)     ? 1.0f : __fdividef((float)DIM, cib + cj0 + acc[2]);
    const float v11 = (ib == j + 1) ? 1.0f : __fdividef((float)DIM, cib + cj1 + acc[3]);

    *(float2*)&out[ia * BSZ + j] = make_float2(v00, v01);
    *(float2*)&out[ib * BSZ + j] = make_float2(v10, v11);

    // ---- transposed block for off-diagonal tiles (T aliases A region) ----
    if (!diag) {
        float* T = (float*)smem;
        __syncthreads();                // all LDSM reads of A done
        T[lia * TP + lj]     = v00;
        T[lia * TP + lj + 1] = v01;
        T[lib * TP + lj]     = v10;
        T[lib * TP + lj + 1] = v11;
        __syncthreads();
        // coalesced store of the transpose: out[j0+r][i0+c] = T[c][r]
        {
            const int r  = tid >> 3;
            const int c4 = (tid & 7) * 4;
            float4 v;
            v.x = T[(c4 + 0) * TP + r];
            v.y = T[(c4 + 1) * TP + r];
            v.z = T[(c4 + 2) * TP + r];
            v.w = T[(c4 + 3) * TP + r];
            *(float4*)&out[(j0 + r) * BSZ + i0 + c4] = v;
        }
    }
}

// ---------------------------------------------------------------------------
extern "C" void kernel_launch(void* const* d_in, const int* in_sizes, int n_in,
                              void* d_out, int out_size) {
    const float* x  = (const float*)d_in[0];
    const float* dc = (const float*)d_in[1];
    const float* ap = (const float*)d_in[2];
    float* out = (float*)d_out;

    cudaFuncSetAttribute(fused_kernel, cudaFuncAttributeMaxDynamicSharedMemorySize, SMEM_BYTES);
    fused_kernel<<<NB * (NB + 1) / 2, 256, SMEM_BYTES>>>(x, dc, ap, out);
}

// round 17
// speedup vs baseline: 1.2901x; 1.2901x over previous
#include <cuda_runtime.h>
#include <cuda_fp16.h>
#include <cstdint>
#include <math.h>

#define BSZ 1024
#define DIM 128

// ---------------- helpers --------------------------------------------------
__device__ __forceinline__ uint32_t smem_u32(const void* p) {
    uint32_t a;
    asm("{ .reg .u64 t; cvta.to.shared.u64 t, %1; cvt.u32.u64 %0, t; }"
        : "=r"(a) : "l"(p));
    return a;
}
#define LDSM4(r0, r1, r2, r3, addr) \
    asm volatile("ldmatrix.sync.aligned.m8n8.x4.shared.b16 {%0,%1,%2,%3}, [%4];" \
                 : "=r"(r0), "=r"(r1), "=r"(r2), "=r"(r3) : "r"(addr))
#define MBARRIER_INIT(addr, cnt) \
    asm volatile("mbarrier.init.shared.b64 [%0], %1;" :: "r"(addr), "r"(cnt) : "memory")
#define MBARRIER_EXPECT_TX(addr, bytes) \
    asm volatile("mbarrier.arrive.expect_tx.shared.b64 _, [%0], %1;" \
                 :: "r"(addr), "r"((uint32_t)(bytes)) : "memory")
#define BULK_G2S(dst, src, bytes, mbar) \
    asm volatile("cp.async.bulk.shared::cta.global.mbarrier::complete_tx::bytes " \
                 "[%0], [%1], %2, [%3];" \
                 :: "r"(dst), "l"(src), "r"((uint32_t)(bytes)), "r"(mbar) : "memory")
#define MBARRIER_WAIT_PARITY(addr, par) do {                                      \
    uint32_t _m = (addr), _p = (par), _d;                                         \
    asm volatile("{\n\t.reg .pred p;\n\t"                                         \
        "mbarrier.try_wait.parity.acquire.cta.shared::cta.b64 p, [%1], %2;\n\t"   \
        "selp.b32 %0, 1, 0, p;\n\t}" : "=r"(_d) : "r"(_m), "r"(_p) : "memory");   \
    if (!_d) {                                                                    \
        asm volatile("{\n\t.reg .pred P1;\n\t"                                    \
            "WL_%=:\n\t"                                                          \
            "mbarrier.try_wait.parity.acquire.cta.shared::cta.b64 P1, [%0], %1, 0x989680;\n\t" \
            "@P1 bra.uni WD_%=;\n\tbra.uni WL_%=;\n\tWD_%=:\n\t}"                 \
            :: "r"(_m), "r"(_p) : "memory");                                      \
    }                                                                             \
} while (0)

__device__ __forceinline__ void mma_f16(float c[4],
                                        uint32_t a0, uint32_t a1, uint32_t a2, uint32_t a3,
                                        uint32_t b0, uint32_t b1) {
    asm volatile(
        "mma.sync.aligned.m16n8k16.row.col.f32.f16.f16.f32 "
        "{%0,%1,%2,%3}, {%4,%5,%6,%7}, {%8,%9}, {%0,%1,%2,%3};"
        : "+f"(c[0]), "+f"(c[1]), "+f"(c[2]), "+f"(c[3])
        : "r"(a0), "r"(a1), "r"(a2), "r"(a3), "r"(b0), "r"(b1));
}

// ---------------------------------------------------------------------------
// Fused kernel, 64(m) x 32(n) tiles over {bj >= 2*bi}: 272 CTAs, 256 threads
// (8 warps, 4m x 2n, warp tile 16x16), ~2 CTAs/SM co-resident.
// Every tile writes its direct block AND its transposed block — overlapping
// writes near the diagonal are bit-identical (symmetric math), so there is
// no diagonal special case.
// Phases: DMA x (48KB, mbar0) -> convert x-part (A negated, + row norms) ->
//   [tid0: DMA dc into reused S, mbar1] -> MMA k0..7 -> wait dc ->
//   convert dc-part -> MMA k8..15 -> epilogue direct + transpose (T aliases S)
//   smem: A @0 (64x528=33792) | B @33792 (32x528=16896) | S @50688 (49152)
//         = 99840 B dynamic  (2 CTAs/SM: 199680 <= 227KB)
// ---------------------------------------------------------------------------
#define ROWB   528
#define OFF_B  33792
#define OFF_S  50688
#define SMEM_BYTES 99840
#define TP 33   // transpose bounce pitch (floats)

__global__ void __launch_bounds__(256, 2)
fused_kernel(const float* __restrict__ x, const float* __restrict__ dc,
             const float* __restrict__ ap, float* __restrict__ out) {
    extern __shared__ __align__(16) char smem[];
    __shared__ __align__(8) uint64_t s_mbar[2];
    __shared__ float s_c[96];

    const int tid = threadIdx.x;
    const int wid = tid >> 5;
    const int lid = tid & 31;
    const int wm  = wid >> 1;          // 0..3 -> m offset wm*16
    const int wn  = wid & 1;           // 0..1 -> n offset wn*16

    // ---- decode tile: bi (64-row block), bj (32-col block), bj >= 2*bi ----
    int bi = 0, rem = blockIdx.x;
    while (rem >= 32 - 2 * bi) { rem -= 32 - 2 * bi; bi++; }
    const int bj = 2 * bi + rem;
    const int i0 = bi * 64;
    const int j0 = bj * 32;

    const uint32_t sb = smem_u32(smem);
    const uint32_t mb = smem_u32(s_mbar);

    // ---- phase 0: stage x (i-rows 32KB + j-rows 16KB) ----
    if (tid == 0) {
        MBARRIER_INIT(mb, 1);
        MBARRIER_INIT(mb + 8, 1);
    }
    __syncthreads();
    if (tid == 0) {
        MBARRIER_EXPECT_TX(mb, 49152);
        BULK_G2S(sb + OFF_S,         x + (size_t)i0 * DIM, 32768, mb);
        BULK_G2S(sb + OFF_S + 32768, x + (size_t)j0 * DIM, 16384, mb);
    }

    const float a  = ap[0];
    const float s1 = sqrtf(2.0f * (1.0f - a));
    const float s2 = sqrtf(a);

    // ---- phase 1: convert x-part (12 rows per warp; rows 0-63 A, 64-95 B) --
    MBARRIER_WAIT_PARITY(mb, 0);
#pragma unroll
    for (int q = 0; q < 12; q++) {
        const int lr = wid * 12 + q;
        const int bside = (lr >= 64);
        const int r  = bside ? (lr - 64) : lr;
        const char* src = smem + OFF_S + (bside ? 32768 : 0) + r * 512;
        char* dst = smem + (bside ? OFF_B : 0) + r * ROWB;
        const uint32_t sgn = bside ? 0u : 0x80008000u;

        const float4 xv = *(const float4*)(src + lid * 16);
        __half zb[4] = { __float2half_rn(s1 * xv.x), __float2half_rn(s1 * xv.y),
                         __float2half_rn(s1 * xv.z), __float2half_rn(s1 * xv.w) };
        uint2 z2 = *(uint2*)zb;
        z2.x ^= sgn; z2.y ^= sgn;
        *(uint2*)(dst + lid * 8) = z2;

        float s = xv.x * xv.x + xv.y * xv.y + xv.z * xv.z + xv.w * xv.w;
#pragma unroll
        for (int o = 16; o; o >>= 1) s += __shfl_down_sync(0xffffffffu, s, o);
        if (lid == 0) s_c[lr] = (1.0f - a) * s;
    }
    __syncthreads();

    // ---- phase 2a: reuse S for dc DMA (lands under MMA k0..7) ----
    if (tid == 0) {
        MBARRIER_EXPECT_TX(mb + 8, 49152);
        BULK_G2S(sb + OFF_S,         dc + (size_t)i0 * DIM, 32768, mb + 8);
        BULK_G2S(sb + OFF_S + 32768, dc + (size_t)j0 * DIM, 16384, mb + 8);
    }

    // ---- mainloop setup ----
    const uint32_t arow = lid & 15;
    const uint32_t acol = (lid >> 4) * 16;
    const uint32_t brow = (lid & 7) | (((lid >> 4) & 1) << 3);
    const uint32_t bcol = ((lid >> 3) & 1) * 16;
    const uint32_t aAd = sb + (wm * 16 + arow) * ROWB + acol;
    const uint32_t bAd = sb + OFF_B + (wn * 16 + brow) * ROWB + bcol;

    float acc[2][4] = {};
    uint32_t F[2][8];

    auto ldf = [&](uint32_t* f, int ks) {
        const uint32_t ko = (uint32_t)ks * 32;
        LDSM4(f[0], f[1], f[2], f[3], aAd + ko);
        LDSM4(f[4], f[5], f[6], f[7], bAd + ko);
    };
    auto domma = [&](uint32_t* f) {
        mma_f16(acc[0], f[0], f[1], f[2], f[3], f[4], f[5]);
        mma_f16(acc[1], f[0], f[1], f[2], f[3], f[6], f[7]);
    };

    // ---- phase 2b: k-steps 0..7 (x columns) ----
    ldf(F[0], 0);
#pragma unroll
    for (int ks = 0; ks < 7; ks++) {
        ldf(F[(ks + 1) & 1], ks + 1);
        domma(F[ks & 1]);
    }
    domma(F[1]);

    // ---- phase 3: convert dc-part ----
    MBARRIER_WAIT_PARITY(mb + 8, 0);
#pragma unroll
    for (int q = 0; q < 12; q++) {
        const int lr = wid * 12 + q;
        const int bside = (lr >= 64);
        const int r  = bside ? (lr - 64) : lr;
        const char* src = smem + OFF_S + (bside ? 32768 : 0) + r * 512;
        char* dst = smem + (bside ? OFF_B : 0) + r * ROWB + 256;

        const float4 dv = *(const float4*)(src + lid * 16);
        __half hb[4] = { __float2half_rn(s2 * __expf(1.0f - dv.x)),
                         __float2half_rn(s2 * __expf(1.0f - dv.y)),
                         __float2half_rn(s2 * __expf(1.0f - dv.z)),
                         __float2half_rn(s2 * __expf(1.0f - dv.w)) };
        *(uint2*)(dst + lid * 8) = *(uint2*)hb;
    }
    __syncthreads();

    // ---- phase 4: k-steps 8..15 (dc columns) ----
    ldf(F[0], 8);
#pragma unroll
    for (int ks = 8; ks < 15; ks++) {
        ldf(F[(ks + 1) & 1], ks + 1);
        domma(F[ks & 1]);
    }
    domma(F[1]);

    // ---- phase 5: epilogue (direct block) ----
    const int g = lid >> 2;
    const int t = lid & 3;
    const int lia = wm * 16 + g;
    const int lib = lia + 8;
    const int ia = i0 + lia;
    const int ib = i0 + lib;
    const float cia = s_c[lia];
    const float cib = s_c[lib];

    float res[2][4];
#pragma unroll
    for (int nf = 0; nf < 2; nf++) {
        const int lj = wn * 16 + nf * 8 + t * 2;
        const int j  = j0 + lj;
        const float cj0 = s_c[64 + lj];
        const float cj1 = s_c[64 + lj + 1];
        const float* s = acc[nf];
        res[nf][0] = (ia == j)     ? 1.0f : __fdividef((float)DIM, cia + cj0 + s[0]);
        res[nf][1] = (ia == j + 1) ? 1.0f : __fdividef((float)DIM, cia + cj1 + s[1]);
        res[nf][2] = (ib == j)     ? 1.0f : __fdividef((float)DIM, cib + cj0 + s[2]);
        res[nf][3] = (ib == j + 1) ? 1.0f : __fdividef((float)DIM, cib + cj1 + s[3]);

        *(float2*)&out[ia * BSZ + j] = make_float2(res[nf][0], res[nf][1]);
        *(float2*)&out[ib * BSZ + j] = make_float2(res[nf][2], res[nf][3]);
    }

    // ---- phase 6: transposed block (always; overlaps are bit-identical) ----
    {
        float* T = (float*)(smem + OFF_S);   // 64 x TP floats = 8448 B
        __syncthreads();                      // dc-convert reads of S complete
#pragma unroll
        for (int nf = 0; nf < 2; nf++) {
            const int lj = wn * 16 + nf * 8 + t * 2;
            T[lia * TP + lj]     = res[nf][0];
            T[lia * TP + lj + 1] = res[nf][1];
            T[lib * TP + lj]     = res[nf][2];
            T[lib * TP + lj + 1] = res[nf][3];
        }
        __syncthreads();
        // out[j0+r][i0+c] = T[c][r] ; 32 rows x 64 cols, coalesced float4
#pragma unroll
        for (int idx = tid; idx < 512; idx += 256) {
            const int r  = idx >> 4;
            const int c4 = (idx & 15) * 4;
            float4 v;
            v.x = T[(c4 + 0) * TP + r];
            v.y = T[(c4 + 1) * TP + r];
            v.z = T[(c4 + 2) * TP + r];
            v.w = T[(c4 + 3) * TP + r];
            *(float4*)&out[(j0 + r) * BSZ + i0 + c4] = v;
        }
    }
}

// ---------------------------------------------------------------------------
extern "C" void kernel_launch(void* const* d_in, const int* in_sizes, int n_in,
                              void* d_out, int out_size) {
    const float* x  = (const float*)d_in[0];
    const float* dc = (const float*)d_in[1];
    const float* ap = (const float*)d_in[2];
    float* out = (float*)d_out;

    cudaFuncSetAttribute(fused_kernel, cudaFuncAttributeMaxDynamicSharedMemorySize, SMEM_BYTES);
    fused_kernel<<<272, 256, SMEM_BYTES>>>(x, dc, ap, out);
}